// round 1
// baseline (speedup 1.0000x reference)
#include <cuda_runtime.h>
#include <cstdint>

#define N_  512
#define C_  128
#define NN_ (N_*N_)

// Scratch (device globals: no allocation allowed in kernel_launch)
__device__ float g_zn[(size_t)NN_*C_];   // LN(z); later reused for LN(o)
__device__ float g_a [(size_t)NN_*C_];   // left projection
__device__ float g_b [(size_t)NN_*C_];   // right projection
__device__ float g_gt[(size_t)NN_*C_];   // output gate sigmoid(zn@w_g^T)
__device__ float g_o [(size_t)NN_*C_];   // triangle einsum result

// ---------------------------------------------------------------------------
// LayerNorm over C=128 (one block of 128 threads per row)
// ---------------------------------------------------------------------------
__global__ __launch_bounds__(128) void ln_kernel(
    const float* __restrict__ x,
    const float* __restrict__ w,
    const float* __restrict__ b,
    float* __restrict__ y)
{
    size_t row = blockIdx.x;
    int c = threadIdx.x;
    float v = x[row*C_ + c];
    float s = v, s2 = v*v;
    #pragma unroll
    for (int o = 16; o; o >>= 1) {
        s  += __shfl_xor_sync(0xffffffffu, s, o);
        s2 += __shfl_xor_sync(0xffffffffu, s2, o);
    }
    __shared__ float sh[8];
    int wid = c >> 5;
    if ((c & 31) == 0) { sh[wid] = s; sh[wid + 4] = s2; }
    __syncthreads();
    s  = sh[0] + sh[1] + sh[2] + sh[3];
    s2 = sh[4] + sh[5] + sh[6] + sh[7];
    float mu  = s  * (1.0f / C_);
    float var = s2 * (1.0f / C_) - mu * mu;
    float inv = rsqrtf(var + 1e-5f);
    y[row*C_ + c] = (v - mu) * inv * w[c] + b[c];
}

// ---------------------------------------------------------------------------
// Projection GEMM: Y[M,128] from X[M,128] @ W^T (W is [out,in] row-major).
// MODE 0: Y = mask[row] * sigmoid(X@W1^T) * (X@W2^T)
// MODE 1: Y = sigmoid(X@W1^T)
// MODE 2: Y = extra[row,col] * (X@W1^T)          (gated output projection)
// Block: 64 rows x 128 cols, 256 threads, thread tile 4x8.
// ---------------------------------------------------------------------------
#define XLD 68
#define WLD 132

template<int MODE>
__global__ __launch_bounds__(256) void proj_kernel(
    const float* __restrict__ X,
    const float* __restrict__ W1,
    const float* __restrict__ W2,
    const float* __restrict__ extra,
    float* __restrict__ Y)
{
    const int BM = 64;
    extern __shared__ float sm[];
    float* xs = sm;                 // [k][r]  transposed, ld=XLD
    float* w1 = xs + C_*XLD;        // [k][oc] transposed, ld=WLD
    float* w2 = w1 + C_*WLD;        // MODE 0 only

    int t = threadIdx.x;
    size_t row0 = (size_t)blockIdx.x * BM;

    for (int idx = t; idx < BM*C_; idx += 256) {
        int r = idx >> 7, k = idx & 127;
        xs[k*XLD + r] = X[(row0 + r)*C_ + k];
    }
    for (int idx = t; idx < C_*C_; idx += 256) {
        int oc = idx >> 7, k = idx & 127;
        w1[k*WLD + oc] = W1[idx];
    }
    if (MODE == 0) {
        for (int idx = t; idx < C_*C_; idx += 256) {
            int oc = idx >> 7, k = idx & 127;
            w2[k*WLD + oc] = W2[idx];
        }
    }
    __syncthreads();

    int r0 = (t & 15) * 4;   // 16 row groups of 4
    int c0 = (t >> 4) * 8;   // 16 col groups of 8

    float acc1[4][8];
    float acc2[4][8];
    #pragma unroll
    for (int i = 0; i < 4; i++)
        #pragma unroll
        for (int j = 0; j < 8; j++) { acc1[i][j] = 0.f; acc2[i][j] = 0.f; }

    #pragma unroll 2
    for (int k = 0; k < C_; k++) {
        float4 xv = *(const float4*)(xs + k*XLD + r0);
        float4 a0 = *(const float4*)(w1 + k*WLD + c0);
        float4 a1 = *(const float4*)(w1 + k*WLD + c0 + 4);
        float xr[4]  = {xv.x, xv.y, xv.z, xv.w};
        float wr1[8] = {a0.x, a0.y, a0.z, a0.w, a1.x, a1.y, a1.z, a1.w};
        #pragma unroll
        for (int i = 0; i < 4; i++)
            #pragma unroll
            for (int j = 0; j < 8; j++)
                acc1[i][j] += xr[i] * wr1[j];
        if (MODE == 0) {
            float4 b0 = *(const float4*)(w2 + k*WLD + c0);
            float4 b1 = *(const float4*)(w2 + k*WLD + c0 + 4);
            float wr2[8] = {b0.x, b0.y, b0.z, b0.w, b1.x, b1.y, b1.z, b1.w};
            #pragma unroll
            for (int i = 0; i < 4; i++)
                #pragma unroll
                for (int j = 0; j < 8; j++)
                    acc2[i][j] += xr[i] * wr2[j];
        }
    }

    #pragma unroll
    for (int i = 0; i < 4; i++) {
        size_t row = row0 + r0 + i;
        float vals[8];
        if (MODE == 0) {
            float m = extra[row];
            #pragma unroll
            for (int j = 0; j < 8; j++) {
                float s = 1.f / (1.f + __expf(-acc1[i][j]));
                vals[j] = m * s * acc2[i][j];
            }
        } else if (MODE == 1) {
            #pragma unroll
            for (int j = 0; j < 8; j++)
                vals[j] = 1.f / (1.f + __expf(-acc1[i][j]));
        } else {
            float4 e0 = *(const float4*)(extra + row*C_ + c0);
            float4 e1 = *(const float4*)(extra + row*C_ + c0 + 4);
            float er[8] = {e0.x, e0.y, e0.z, e0.w, e1.x, e1.y, e1.z, e1.w};
            #pragma unroll
            for (int j = 0; j < 8; j++)
                vals[j] = er[j] * acc1[i][j];
        }
        *(float4*)(Y + row*C_ + c0)     = make_float4(vals[0], vals[1], vals[2], vals[3]);
        *(float4*)(Y + row*C_ + c0 + 4) = make_float4(vals[4], vals[5], vals[6], vals[7]);
    }
}

// ---------------------------------------------------------------------------
// Triangle einsum: O[i,j,c] = sum_k A[i,k,c] * B[j,k,c]
// Block: 16x16 (i,j) tile, 512 threads (c = t&127, q = t>>7 picks 4 j's).
// cp.async double-buffered k-panels (KT=4).
// ---------------------------------------------------------------------------
__device__ __forceinline__ void cp16(float* dst, const float* src) {
    unsigned s = (unsigned)__cvta_generic_to_shared(dst);
    asm volatile("cp.async.cg.shared.global [%0], [%1], 16;\n" :: "r"(s), "l"(src));
}

#define TI_ 16
#define TJ_ 16
#define KT_ 4
#define SZ_ (TI_*KT_*C_)   // 8192 floats = 32KB per tensor per stage

__global__ __launch_bounds__(512) void tri_kernel(
    const float* __restrict__ A,
    const float* __restrict__ B,
    float* __restrict__ O)
{
    extern __shared__ float sm[];
    float* as = sm;            // 2 * SZ_
    float* bs = sm + 2*SZ_;    // 2 * SZ_

    int t = threadIdx.x;
    int c = t & 127;
    int q = t >> 7;            // 0..3
    int i0 = blockIdx.y * TI_;
    int j0 = blockIdx.x * TJ_;
    const int NP = N_ / KT_;   // 128 panels

    auto stage = [&](int kp, int s) {
        #pragma unroll
        for (int n = 0; n < 4; n++) {
            int idx = t + n*512;        // 0..2047 float4 slots
            int p   = idx >> 5;         // (ti*KT+kk), 0..63
            int c4  = idx & 31;
            int ti  = p >> 2, kk = p & 3;
            cp16(as + (size_t)s*SZ_ + idx*4,
                 A + ((size_t)(i0+ti)*N_ + kp*KT_ + kk)*C_ + c4*4);
            cp16(bs + (size_t)s*SZ_ + idx*4,
                 B + ((size_t)(j0+ti)*N_ + kp*KT_ + kk)*C_ + c4*4);
        }
        asm volatile("cp.async.commit_group;\n");
    };

    float acc[TI_][4];
    #pragma unroll
    for (int i = 0; i < TI_; i++)
        #pragma unroll
        for (int j = 0; j < 4; j++) acc[i][j] = 0.f;

    stage(0, 0);
    for (int kp = 0; kp < NP; kp++) {
        if (kp + 1 < NP) {
            stage(kp + 1, (kp + 1) & 1);
            asm volatile("cp.async.wait_group 1;\n");
        } else {
            asm volatile("cp.async.wait_group 0;\n");
        }
        __syncthreads();
        const float* ap = as + (size_t)(kp & 1)*SZ_ + c;
        const float* bp = bs + (size_t)(kp & 1)*SZ_ + c;
        #pragma unroll
        for (int kk = 0; kk < KT_; kk++) {
            float av[TI_];
            #pragma unroll
            for (int ti = 0; ti < TI_; ti++)
                av[ti] = ap[(ti*KT_ + kk)*C_];
            float bv[4];
            #pragma unroll
            for (int tj = 0; tj < 4; tj++)
                bv[tj] = bp[((q*4 + tj)*KT_ + kk)*C_];
            #pragma unroll
            for (int ti = 0; ti < TI_; ti++)
                #pragma unroll
                for (int tj = 0; tj < 4; tj++)
                    acc[ti][tj] += av[ti] * bv[tj];
        }
        __syncthreads();
    }

    #pragma unroll
    for (int ti = 0; ti < TI_; ti++)
        #pragma unroll
        for (int tj = 0; tj < 4; tj++)
            O[((size_t)(i0+ti)*N_ + (j0 + q*4 + tj))*C_ + c] = acc[ti][tj];
}

// ---------------------------------------------------------------------------
extern "C" void kernel_launch(void* const* d_in, const int* in_sizes, int n_in,
                              void* d_out, int out_size)
{
    const float* z      = (const float*)d_in[0];
    const float* mask   = (const float*)d_in[1];
    const float* ln_i_w = (const float*)d_in[2];
    const float* ln_i_b = (const float*)d_in[3];
    const float* ln_o_w = (const float*)d_in[4];
    const float* ln_o_b = (const float*)d_in[5];
    const float* w_pa   = (const float*)d_in[6];
    const float* w_pb   = (const float*)d_in[7];
    const float* w_ga   = (const float*)d_in[8];
    const float* w_gb   = (const float*)d_in[9];
    const float* w_g    = (const float*)d_in[10];
    const float* w_o    = (const float*)d_in[11];
    float* out = (float*)d_out;

    float *zn, *a, *b, *gt, *o;
    cudaGetSymbolAddress((void**)&zn, g_zn);
    cudaGetSymbolAddress((void**)&a,  g_a);
    cudaGetSymbolAddress((void**)&b,  g_b);
    cudaGetSymbolAddress((void**)&gt, g_gt);
    cudaGetSymbolAddress((void**)&o,  g_o);

    const int SMEM0 = (C_*XLD + 2*C_*WLD) * 4;  // 169984
    const int SMEM1 = (C_*XLD + 1*C_*WLD) * 4;  // 102400
    const int SMEMT = 4 * SZ_ * 4;              // 131072
    cudaFuncSetAttribute(proj_kernel<0>, cudaFuncAttributeMaxDynamicSharedMemorySize, SMEM0);
    cudaFuncSetAttribute(proj_kernel<1>, cudaFuncAttributeMaxDynamicSharedMemorySize, SMEM1);
    cudaFuncSetAttribute(proj_kernel<2>, cudaFuncAttributeMaxDynamicSharedMemorySize, SMEM1);
    cudaFuncSetAttribute(tri_kernel,     cudaFuncAttributeMaxDynamicSharedMemorySize, SMEMT);

    // 1) zn = LN(z)
    ln_kernel<<<NN_, 128>>>(z, ln_i_w, ln_i_b, zn);
    // 2) a = mask * sigmoid(zn@w_ga^T) * (zn@w_pa^T)
    proj_kernel<0><<<NN_/64, 256, SMEM0>>>(zn, w_ga, w_pa, mask, a);
    // 3) b = mask * sigmoid(zn@w_gb^T) * (zn@w_pb^T)
    proj_kernel<0><<<NN_/64, 256, SMEM0>>>(zn, w_gb, w_pb, mask, b);
    // 4) gate = sigmoid(zn@w_g^T)
    proj_kernel<1><<<NN_/64, 256, SMEM1>>>(zn, w_g, nullptr, nullptr, gt);
    // 5) o[i,j,c] = sum_k a[i,k,c]*b[j,k,c]
    tri_kernel<<<dim3(N_/TJ_, N_/TI_), 512, SMEMT>>>(a, b, o);
    // 6) on = LN(o)  (reuse zn buffer)
    ln_kernel<<<NN_, 128>>>(o, ln_o_w, ln_o_b, zn);
    // 7) out = gate * (on @ w_o^T)
    proj_kernel<2><<<NN_/64, 256, SMEM1>>>(zn, w_o, nullptr, gt, out);
}

// round 2
// speedup vs baseline: 1.6190x; 1.6190x over previous
#include <cuda_runtime.h>
#include <cstdint>

#define N_  512
#define C_  128
#define NN_ (N_*N_)

// Scratch device globals (no allocation allowed in kernel_launch)
__device__ float g_zn[(size_t)NN_*C_];   // LN(z); reused as ot (c-major einsum out)
__device__ float g_a [(size_t)NN_*C_];   // left projection; reused as o (row-major)
__device__ float g_b [(size_t)NN_*C_];   // right projection; reused as on (LN(o))
__device__ float g_gt[(size_t)NN_*C_];   // output gate
__device__ float g_at[(size_t)NN_*C_];   // a transposed to [c][i][k]
__device__ float g_bt[(size_t)NN_*C_];   // b transposed to [c][j][k]

// ---------------------------------------------------------------------------
// helpers
// ---------------------------------------------------------------------------
__device__ __forceinline__ float sigf(float x) { return 1.f / (1.f + __expf(-x)); }

// split fp32 into hi/lo tf32 (3xTF32 scheme)
__device__ __forceinline__ void split2(float x, uint32_t& hi, uint32_t& lo) {
    asm("cvt.rna.tf32.f32 %0, %1;" : "=r"(hi) : "f"(x));
    float r = x - __uint_as_float(hi);
    asm("cvt.rna.tf32.f32 %0, %1;" : "=r"(lo) : "f"(r));
}

__device__ __forceinline__ void mma_tf32(float* c, const uint32_t* a, const uint32_t* b) {
    asm volatile(
        "mma.sync.aligned.m16n8k8.row.col.f32.tf32.tf32.f32 "
        "{%0,%1,%2,%3},{%4,%5,%6,%7},{%8,%9},{%0,%1,%2,%3};\n"
        : "+f"(c[0]), "+f"(c[1]), "+f"(c[2]), "+f"(c[3])
        : "r"(a[0]), "r"(a[1]), "r"(a[2]), "r"(a[3]), "r"(b[0]), "r"(b[1]));
}

__device__ __forceinline__ void cp16(float* dst, const float* src) {
    unsigned s = (unsigned)__cvta_generic_to_shared(dst);
    asm volatile("cp.async.cg.shared.global [%0], [%1], 16;\n" :: "r"(s), "l"(src));
}

// ---------------------------------------------------------------------------
// LayerNorm over C=128 (one block of 128 threads per row)
// ---------------------------------------------------------------------------
__global__ __launch_bounds__(128) void ln_kernel(
    const float* __restrict__ x, const float* __restrict__ w,
    const float* __restrict__ b, float* __restrict__ y)
{
    size_t row = blockIdx.x;
    int c = threadIdx.x;
    float v = x[row*C_ + c];
    float s = v, s2 = v*v;
    #pragma unroll
    for (int o = 16; o; o >>= 1) {
        s  += __shfl_xor_sync(0xffffffffu, s, o);
        s2 += __shfl_xor_sync(0xffffffffu, s2, o);
    }
    __shared__ float sh[8];
    int wid = c >> 5;
    if ((c & 31) == 0) { sh[wid] = s; sh[wid + 4] = s2; }
    __syncthreads();
    s  = sh[0] + sh[1] + sh[2] + sh[3];
    s2 = sh[4] + sh[5] + sh[6] + sh[7];
    float mu  = s  * (1.0f / C_);
    float var = s2 * (1.0f / C_) - mu * mu;
    float inv = rsqrtf(var + 1e-5f);
    y[row*C_ + c] = (v - mu) * inv * w[c] + b[c];
}

// ---------------------------------------------------------------------------
// Tiled transpose: out[c][r] = in[r][c],  in is R x C (both mult of 32)
// ---------------------------------------------------------------------------
__global__ __launch_bounds__(256) void transpose_kernel(
    const float* __restrict__ in, float* __restrict__ out, int R, int C)
{
    __shared__ float tile[32][33];
    size_t c0 = (size_t)blockIdx.x * 32, r0 = (size_t)blockIdx.y * 32;
    int tx = threadIdx.x, ty = threadIdx.y;   // 32 x 8
    #pragma unroll
    for (int k = 0; k < 4; k++)
        tile[ty + k*8][tx] = in[(r0 + ty + k*8) * C + c0 + tx];
    __syncthreads();
    #pragma unroll
    for (int k = 0; k < 4; k++)
        out[(c0 + ty + k*8) * R + r0 + tx] = tile[tx][ty + k*8];
}

// ---------------------------------------------------------------------------
// Projection GEMM via tensor cores (3xTF32).
// X[M,128] @ W^T, W stored [out,in] row-major.
// MODE 0: Y = mask[row] * sigmoid(X@W1^T) * (X@W2^T)
// MODE 1: Y = sigmoid(X@W1^T)
// MODE 2: Y = extra[row,col] * (X@W1^T)
// Block: BM=128 rows, 16 warps (4 M x 4 N), warp tile 32x32 per matrix.
// ---------------------------------------------------------------------------
#define PLD 132

template<int MODE>
__global__ __launch_bounds__(512, 1) void proj_mma(
    const float* __restrict__ X,  const float* __restrict__ W1,
    const float* __restrict__ W2, const float* __restrict__ extra,
    float* __restrict__ Y)
{
    extern __shared__ float sm[];
    float* xs  = sm;                 // [128][PLD]
    float* w1s = xs + 128*PLD;       // [128][PLD]
    float* w2s = w1s + 128*PLD;      // MODE 0 only

    int t = threadIdx.x;
    size_t row0 = (size_t)blockIdx.x * 128;

    for (int idx = t; idx < 128*32; idx += 512) {
        int r = idx >> 5, c4 = idx & 31;
        float4 v = *(const float4*)(X + (row0 + r)*C_ + c4*4);
        float* d = xs + r*PLD + c4*4;
        d[0]=v.x; d[1]=v.y; d[2]=v.z; d[3]=v.w;
    }
    for (int idx = t; idx < 128*32; idx += 512) {
        int r = idx >> 5, c4 = idx & 31;
        float4 v = *(const float4*)(W1 + r*C_ + c4*4);
        float* d = w1s + r*PLD + c4*4;
        d[0]=v.x; d[1]=v.y; d[2]=v.z; d[3]=v.w;
        if (MODE == 0) {
            float4 u = *(const float4*)(W2 + r*C_ + c4*4);
            float* e = w2s + r*PLD + c4*4;
            e[0]=u.x; e[1]=u.y; e[2]=u.z; e[3]=u.w;
        }
    }
    __syncthreads();

    int warp = t >> 5, lane = t & 31;
    int g = lane >> 2, tg = lane & 3;
    int m0 = (warp & 3) * 32;     // 4 M-warps
    int n0 = (warp >> 2) * 32;    // 4 N-warps, 32 output channels each

    float acc1[2][4][4];
    float acc2[2][4][4];
    #pragma unroll
    for (int mt = 0; mt < 2; mt++)
        #pragma unroll
        for (int nt = 0; nt < 4; nt++)
            #pragma unroll
            for (int q = 0; q < 4; q++) { acc1[mt][nt][q] = 0.f; acc2[mt][nt][q] = 0.f; }

    #pragma unroll 4
    for (int k0 = 0; k0 < 128; k0 += 8) {
        uint32_t Ah[2][4], Al[2][4];
        #pragma unroll
        for (int mt = 0; mt < 2; mt++) {
            int r = m0 + mt*16 + g;
            split2(xs[r*PLD + k0 + tg],          Ah[mt][0], Al[mt][0]);
            split2(xs[(r+8)*PLD + k0 + tg],      Ah[mt][1], Al[mt][1]);
            split2(xs[r*PLD + k0 + tg + 4],      Ah[mt][2], Al[mt][2]);
            split2(xs[(r+8)*PLD + k0 + tg + 4],  Ah[mt][3], Al[mt][3]);
        }
        #pragma unroll
        for (int nt = 0; nt < 4; nt++) {
            int n = n0 + nt*8 + g;
            uint32_t Bh[2], Bl[2];
            split2(w1s[n*PLD + k0 + tg],     Bh[0], Bl[0]);
            split2(w1s[n*PLD + k0 + tg + 4], Bh[1], Bl[1]);
            #pragma unroll
            for (int mt = 0; mt < 2; mt++) {
                mma_tf32(acc1[mt][nt], Ah[mt], Bh);
                mma_tf32(acc1[mt][nt], Al[mt], Bh);
                mma_tf32(acc1[mt][nt], Ah[mt], Bl);
            }
            if (MODE == 0) {
                split2(w2s[n*PLD + k0 + tg],     Bh[0], Bl[0]);
                split2(w2s[n*PLD + k0 + tg + 4], Bh[1], Bl[1]);
                #pragma unroll
                for (int mt = 0; mt < 2; mt++) {
                    mma_tf32(acc2[mt][nt], Ah[mt], Bh);
                    mma_tf32(acc2[mt][nt], Al[mt], Bh);
                    mma_tf32(acc2[mt][nt], Ah[mt], Bl);
                }
            }
        }
    }

    #pragma unroll
    for (int mt = 0; mt < 2; mt++) {
        #pragma unroll
        for (int nt = 0; nt < 4; nt++) {
            size_t rl = row0 + m0 + mt*16 + g;
            size_t rh = rl + 8;
            int col = n0 + nt*8 + 2*tg;
            float2 v0, v1;
            if (MODE == 0) {
                float ml = extra[rl], mh = extra[rh];
                v0.x = ml * sigf(acc1[mt][nt][0]) * acc2[mt][nt][0];
                v0.y = ml * sigf(acc1[mt][nt][1]) * acc2[mt][nt][1];
                v1.x = mh * sigf(acc1[mt][nt][2]) * acc2[mt][nt][2];
                v1.y = mh * sigf(acc1[mt][nt][3]) * acc2[mt][nt][3];
            } else if (MODE == 1) {
                v0.x = sigf(acc1[mt][nt][0]); v0.y = sigf(acc1[mt][nt][1]);
                v1.x = sigf(acc1[mt][nt][2]); v1.y = sigf(acc1[mt][nt][3]);
            } else {
                float2 el = *(const float2*)(extra + rl*C_ + col);
                float2 eh = *(const float2*)(extra + rh*C_ + col);
                v0.x = el.x * acc1[mt][nt][0]; v0.y = el.y * acc1[mt][nt][1];
                v1.x = eh.x * acc1[mt][nt][2]; v1.y = eh.y * acc1[mt][nt][3];
            }
            *(float2*)(Y + rl*C_ + col) = v0;
            *(float2*)(Y + rh*C_ + col) = v1;
        }
    }
}

// ---------------------------------------------------------------------------
// Triangle einsum as 128 per-channel GEMMs (tensor cores, 3xTF32):
// Ot[c][i][j] = sum_k At[c][i][k] * Bt[c][j][k]
// Block = 128x128 output tile per channel, 8 warps (4M x 2N), warp 32x64.
// BK=32, cp.async double-buffered.
// ---------------------------------------------------------------------------
#define TLD 36
#define TSTG (128*TLD)

__global__ __launch_bounds__(256, 2) void tri_mma(
    const float* __restrict__ At, const float* __restrict__ Bt,
    float* __restrict__ Ot)
{
    extern __shared__ float sm[];
    float* as = sm;            // [2][TSTG]
    float* bs = sm + 2*TSTG;   // [2][TSTG]

    int t = threadIdx.x;
    size_t coff = (size_t)blockIdx.z * ((size_t)N_*N_);
    const float* A = At + coff + (size_t)blockIdx.y * 128 * N_;
    const float* B = Bt + coff + (size_t)blockIdx.x * 128 * N_;

    auto stage = [&](int kc, int s) {
        float* ad = as + s*TSTG;
        float* bd = bs + s*TSTG;
        #pragma unroll
        for (int n = 0; n < 4; n++) {
            int idx = t + n*256;
            int r = idx >> 3, c4 = idx & 7;
            cp16(ad + r*TLD + c4*4, A + (size_t)r*N_ + kc*32 + c4*4);
            cp16(bd + r*TLD + c4*4, B + (size_t)r*N_ + kc*32 + c4*4);
        }
        asm volatile("cp.async.commit_group;\n");
    };

    int warp = t >> 5, lane = t & 31;
    int g = lane >> 2, tg = lane & 3;
    int m0 = (warp & 3) * 32;
    int n0 = (warp >> 2) * 64;

    float acc[2][8][4];
    #pragma unroll
    for (int mt = 0; mt < 2; mt++)
        #pragma unroll
        for (int nt = 0; nt < 8; nt++)
            #pragma unroll
            for (int q = 0; q < 4; q++) acc[mt][nt][q] = 0.f;

    stage(0, 0);
    for (int kc = 0; kc < 16; kc++) {
        if (kc < 15) {
            stage(kc + 1, (kc + 1) & 1);
            asm volatile("cp.async.wait_group 1;\n");
        } else {
            asm volatile("cp.async.wait_group 0;\n");
        }
        __syncthreads();
        const float* ap = as + (kc & 1)*TSTG;
        const float* bp = bs + (kc & 1)*TSTG;
        #pragma unroll
        for (int kk = 0; kk < 4; kk++) {
            int k0 = kk * 8;
            uint32_t Ah[2][4], Al[2][4];
            #pragma unroll
            for (int mt = 0; mt < 2; mt++) {
                int r = m0 + mt*16 + g;
                split2(ap[r*TLD + k0 + tg],         Ah[mt][0], Al[mt][0]);
                split2(ap[(r+8)*TLD + k0 + tg],     Ah[mt][1], Al[mt][1]);
                split2(ap[r*TLD + k0 + tg + 4],     Ah[mt][2], Al[mt][2]);
                split2(ap[(r+8)*TLD + k0 + tg + 4], Ah[mt][3], Al[mt][3]);
            }
            #pragma unroll
            for (int nt = 0; nt < 8; nt++) {
                int n = n0 + nt*8 + g;
                uint32_t Bh[2], Bl[2];
                split2(bp[n*TLD + k0 + tg],     Bh[0], Bl[0]);
                split2(bp[n*TLD + k0 + tg + 4], Bh[1], Bl[1]);
                #pragma unroll
                for (int mt = 0; mt < 2; mt++) {
                    mma_tf32(acc[mt][nt], Ah[mt], Bh);
                    mma_tf32(acc[mt][nt], Al[mt], Bh);
                    mma_tf32(acc[mt][nt], Ah[mt], Bl);
                }
            }
        }
        __syncthreads();
    }

    float* O = Ot + coff;
    int i_base = blockIdx.y * 128 + m0;
    int j_base = blockIdx.x * 128 + n0;
    #pragma unroll
    for (int mt = 0; mt < 2; mt++) {
        int r = i_base + mt*16 + g;
        #pragma unroll
        for (int nt = 0; nt < 8; nt++) {
            int cl = j_base + nt*8 + 2*tg;
            *(float2*)(O + (size_t)r*N_ + cl)     = make_float2(acc[mt][nt][0], acc[mt][nt][1]);
            *(float2*)(O + (size_t)(r+8)*N_ + cl) = make_float2(acc[mt][nt][2], acc[mt][nt][3]);
        }
    }
}

// ---------------------------------------------------------------------------
extern "C" void kernel_launch(void* const* d_in, const int* in_sizes, int n_in,
                              void* d_out, int out_size)
{
    const float* z      = (const float*)d_in[0];
    const float* mask   = (const float*)d_in[1];
    const float* ln_i_w = (const float*)d_in[2];
    const float* ln_i_b = (const float*)d_in[3];
    const float* ln_o_w = (const float*)d_in[4];
    const float* ln_o_b = (const float*)d_in[5];
    const float* w_pa   = (const float*)d_in[6];
    const float* w_pb   = (const float*)d_in[7];
    const float* w_ga   = (const float*)d_in[8];
    const float* w_gb   = (const float*)d_in[9];
    const float* w_g    = (const float*)d_in[10];
    const float* w_o    = (const float*)d_in[11];
    float* out = (float*)d_out;

    float *zn, *a, *b, *gt, *at, *bt;
    cudaGetSymbolAddress((void**)&zn, g_zn);
    cudaGetSymbolAddress((void**)&a,  g_a);
    cudaGetSymbolAddress((void**)&b,  g_b);
    cudaGetSymbolAddress((void**)&gt, g_gt);
    cudaGetSymbolAddress((void**)&at, g_at);
    cudaGetSymbolAddress((void**)&bt, g_bt);
    float* ot = zn;   // reuse: zn dead after projections
    float* o  = a;    // reuse: a dead after transpose
    float* on = b;    // reuse: b dead after transpose

    const int SMEM_P0 = 3 * 128 * PLD * 4;  // 202752
    const int SMEM_P1 = 2 * 128 * PLD * 4;  // 135168
    const int SMEM_T  = 4 * TSTG * 4;       // 73728
    cudaFuncSetAttribute(proj_mma<0>, cudaFuncAttributeMaxDynamicSharedMemorySize, SMEM_P0);
    cudaFuncSetAttribute(proj_mma<1>, cudaFuncAttributeMaxDynamicSharedMemorySize, SMEM_P1);
    cudaFuncSetAttribute(proj_mma<2>, cudaFuncAttributeMaxDynamicSharedMemorySize, SMEM_P1);
    cudaFuncSetAttribute(tri_mma,     cudaFuncAttributeMaxDynamicSharedMemorySize, SMEM_T);

    // 1) zn = LN(z)
    ln_kernel<<<NN_, 128>>>(z, ln_i_w, ln_i_b, zn);
    // 2) a = mask * sigmoid(zn@w_ga^T) * (zn@w_pa^T)
    proj_mma<0><<<NN_/128, 512, SMEM_P0>>>(zn, w_ga, w_pa, mask, a);
    // 3) b = mask * sigmoid(zn@w_gb^T) * (zn@w_pb^T)
    proj_mma<0><<<NN_/128, 512, SMEM_P0>>>(zn, w_gb, w_pb, mask, b);
    // 4) gate = sigmoid(zn@w_g^T)
    proj_mma<1><<<NN_/128, 512, SMEM_P1>>>(zn, w_g, nullptr, nullptr, gt);
    // 5) transpose a,b to channel-major [c][row][k]
    transpose_kernel<<<dim3(C_/32, NN_/32), dim3(32, 8)>>>(a, at, NN_, C_);
    transpose_kernel<<<dim3(C_/32, NN_/32), dim3(32, 8)>>>(b, bt, NN_, C_);
    // 6) Ot[c][i][j] = sum_k At[c][i][k]*Bt[c][j][k]
    tri_mma<<<dim3(N_/128, N_/128, C_), 256, SMEM_T>>>(at, bt, ot);
    // 7) transpose back to row-major o[(i,j)][c]
    transpose_kernel<<<dim3(NN_/32, C_/32), dim3(32, 8)>>>(ot, o, C_, NN_);
    // 8) on = LN(o)
    ln_kernel<<<NN_, 128>>>(o, ln_o_w, ln_o_b, on);
    // 9) out = gate * (on @ w_o^T)
    proj_mma<2><<<NN_/128, 512, SMEM_P1>>>(on, w_o, nullptr, gt, out);
}